// round 1
// baseline (speedup 1.0000x reference)
#include <cuda_runtime.h>
#include <cuda_bf16.h>

// FFT long conv: y[b, :] = (1/N) * linear_conv(x[b], h[b])[:L],  N = 2L = 16384
// One CTA per row. Complex packing trick: z = x + i*h, one forward FFT gives
// both spectra; pointwise product with Hermitian symmetry; one inverse FFT.
// Radix-4 throughout (16384 = 4^7): 7 fwd DIF passes + 7 inv DIT passes in smem.

#define LCONV 8192
#define NFFT  16384
#define LOGN  14
#define NTHR  512
#define NBF   (NFFT / 4)          // butterflies per pass = 4096
#define SCALE_F (1.0f / ((float)NFFT * (float)NFFT))

__device__ __forceinline__ float2 cmul(float2 a, float2 b) {
    return make_float2(fmaf(a.x, b.x, -a.y * b.y),
                       fmaf(a.x, b.y,  a.y * b.x));
}

// base-4 digit reversal of a 14-bit (7-digit) index:
// full 14-bit bit-reversal, then swap bits within each 2-bit digit.
__device__ __forceinline__ int rev4_14(int k) {
    unsigned r = __brev((unsigned)k) >> 18;
    return (int)(((r & 0x1555u) << 1) | ((r & 0x2AAAu) >> 1));
}

extern "C" __global__ void __launch_bounds__(NTHR, 1)
fftconv_kernel(const float* __restrict__ xin,
               const float* __restrict__ hin,
               float* __restrict__ yout)
{
    extern __shared__ float2 sm[];
    float2* z  = sm;          // NFFT complex points (128 KB)
    float2* tw = sm + NFFT;   // NFFT/4 twiddles    (32 KB)

    const int tid = threadIdx.x;
    const size_t row = blockIdx.x;

    // ---- twiddle table: tw[t] = exp(-2*pi*i*t/N), t in [0, N/4) ----
    {
        const float step = -6.28318530717958647692f / (float)NFFT;
        #pragma unroll
        for (int t = tid; t < NFFT / 4; t += NTHR) {
            float s, c;
            __sincosf(step * (float)t, &s, &c);
            tw[t] = make_float2(c, s);
        }
    }

    // ---- load + pack: z = x + i*h, zero-pad to N ----
    {
        const float* xr = xin + row * LCONV;
        const float* hr = hin + row * LCONV;
        #pragma unroll
        for (int i = tid; i < LCONV; i += NTHR)
            z[i] = make_float2(xr[i], hr[i]);
        #pragma unroll
        for (int i = LCONV + tid; i < NFFT; i += NTHR)
            z[i] = make_float2(0.0f, 0.0f);
    }
    __syncthreads();

    // ---- forward radix-4 DIF: natural in -> rev4 out ----
    for (int lm = LOGN; lm >= 2; lm -= 2) {
        const int lq = lm - 2;
        const int qm = (1 << lq) - 1;
        const int q  = 1 << lq;
        const int ts = LOGN - lm;     // twiddle stride shift
        #pragma unroll 4
        for (int u = 0; u < NBF / NTHR; ++u) {
            const int i  = tid + u * NTHR;
            const int j  = i & qm;
            const int p0 = ((i >> lq) << lm) + j;
            const int p1 = p0 + q, p2 = p1 + q, p3 = p2 + q;

            float2 a0 = z[p0], a1 = z[p1], a2 = z[p2], a3 = z[p3];
            float2 w1 = tw[j << ts];
            float2 w2 = cmul(w1, w1);
            float2 w3 = cmul(w2, w1);

            float2 t02p = make_float2(a0.x + a2.x, a0.y + a2.y);
            float2 t02m = make_float2(a0.x - a2.x, a0.y - a2.y);
            float2 t13p = make_float2(a1.x + a3.x, a1.y + a3.y);
            float2 t13m = make_float2(a1.x - a3.x, a1.y - a3.y);
            float2 mi13 = make_float2(t13m.y, -t13m.x);       // -i*(a1-a3)

            float2 b0 = make_float2(t02p.x + t13p.x, t02p.y + t13p.y);
            float2 b1 = make_float2(t02m.x + mi13.x, t02m.y + mi13.y);
            float2 b2 = make_float2(t02p.x - t13p.x, t02p.y - t13p.y);
            float2 b3 = make_float2(t02m.x - mi13.x, t02m.y - mi13.y);

            z[p0] = b0;
            z[p1] = cmul(b1, w1);
            z[p2] = cmul(b2, w2);
            z[p3] = cmul(b3, w3);
        }
        __syncthreads();
    }

    // ---- pointwise: unpack X,H; Y = X*H*SCALE; Hermitian fill ----
    // storage A[p] = Z[rev4(p)]; pair (k, N-k) handled by one thread.
    #pragma unroll
    for (int k = tid; k < NFFT / 2; k += NTHR) {
        if (k == 0) {
            float2 z0 = z[0];                       // rev4(0) = 0
            z[0] = make_float2(z0.x * z0.y * SCALE_F, 0.0f);
            float2 zm = z[2];                       // rev4(N/2) = 2
            z[2] = make_float2(zm.x * zm.y * SCALE_F, 0.0f);
        } else {
            const int ka = rev4_14(k);
            const int kb = rev4_14(NFFT - k);
            float2 za = z[ka], zb = z[kb];
            float2 X = make_float2(0.5f * (za.x + zb.x), 0.5f * (za.y - zb.y));
            float2 d = make_float2(za.x - zb.x, za.y + zb.y);
            float2 H = make_float2(0.5f * d.y, -0.5f * d.x);  // -i*d/2
            float2 Y = cmul(X, H);
            Y.x *= SCALE_F; Y.y *= SCALE_F;
            z[ka] = Y;
            z[kb] = make_float2(Y.x, -Y.y);         // Y[N-k] = conj(Y[k])
        }
    }
    __syncthreads();

    // ---- inverse radix-4 DIT: rev4 in -> natural out (unscaled) ----
    for (int lm = 2; lm <= LOGN; lm += 2) {
        const int lq = lm - 2;
        const int qm = (1 << lq) - 1;
        const int q  = 1 << lq;
        const int ts = LOGN - lm;
        #pragma unroll 4
        for (int u = 0; u < NBF / NTHR; ++u) {
            const int i  = tid + u * NTHR;
            const int j  = i & qm;
            const int p0 = ((i >> lq) << lm) + j;
            const int p1 = p0 + q, p2 = p1 + q, p3 = p2 + q;

            float2 wc = tw[j << ts];
            float2 w1 = make_float2(wc.x, -wc.y);   // conj: e^{+2*pi*i*...}
            float2 w2 = cmul(w1, w1);
            float2 w3 = cmul(w2, w1);

            float2 c0 = z[p0];
            float2 c1 = cmul(z[p1], w1);
            float2 c2 = cmul(z[p2], w2);
            float2 c3 = cmul(z[p3], w3);

            float2 s02p = make_float2(c0.x + c2.x, c0.y + c2.y);
            float2 s02m = make_float2(c0.x - c2.x, c0.y - c2.y);
            float2 s13p = make_float2(c1.x + c3.x, c1.y + c3.y);
            float2 s13m = make_float2(c1.x - c3.x, c1.y - c3.y);
            float2 pi13 = make_float2(-s13m.y, s13m.x);       // +i*(c1-c3)

            z[p0] = make_float2(s02p.x + s13p.x, s02p.y + s13p.y);
            z[p1] = make_float2(s02m.x + pi13.x, s02m.y + pi13.y);
            z[p2] = make_float2(s02p.x - s13p.x, s02p.y - s13p.y);
            z[p3] = make_float2(s02m.x - pi13.x, s02m.y - pi13.y);
        }
        __syncthreads();
    }

    // ---- store real part of first L points ----
    {
        float* yr = yout + row * LCONV;
        #pragma unroll
        for (int i = tid; i < LCONV; i += NTHR)
            yr[i] = z[i].x;
    }
}

extern "C" void kernel_launch(void* const* d_in, const int* in_sizes, int n_in,
                              void* d_out, int out_size) {
    const float* x = (const float*)d_in[0];
    const float* h = (const float*)d_in[1];
    float* y = (float*)d_out;

    const int B = in_sizes[0] / LCONV;
    const size_t smem_bytes = (size_t)(NFFT + NFFT / 4) * sizeof(float2);  // 160 KB

    cudaFuncSetAttribute(fftconv_kernel,
                         cudaFuncAttributeMaxDynamicSharedMemorySize,
                         (int)smem_bytes);
    fftconv_kernel<<<B, NTHR, smem_bytes>>>(x, h, y);
}

// round 3
// speedup vs baseline: 2.0922x; 2.0922x over previous
#include <cuda_runtime.h>
#include <cuda_bf16.h>

// FFT long conv: y[b,:] = (1/N) * linear_conv(x[b], h[b])[:L], N = 2L = 16384.
// One CTA per row. z = x + i*h packing; forward radix-4 DIF; Hermitian pointwise;
// inverse radix-4 DIT. Optimizations vs round-1:
//  - pairs of radix-4 stages fused into register-resident radix-16 (14 -> 8 smem stages)
//  - smem padding idx + (idx>>4): all butterfly patterns conflict-free
//  - pointwise enumerated by ADDRESS (digit-reversed domain) so accesses are
//    sequential, not rev4-scattered (kills the 16-way conflict hot spot)
// (Resubmission of round-2 kernel: previous bench hit a container infra failure,
//  kernel never executed. Code re-audited for bounds/fusion/pairing correctness.)

#define LCONV 8192
#define NFFT  16384
#define LOGN  14
#define NTHR  512
#define SCALE_F (1.0f / ((float)NFFT * (float)NFFT))

#define PADZ(i) ((i) + ((i) >> 4))
#define ZPAD  (NFFT + (NFFT >> 4))     // 17408 float2

__device__ __forceinline__ float2 cmul(float2 a, float2 b) {
    return make_float2(fmaf(a.x, b.x, -a.y * b.y),
                       fmaf(a.x, b.y,  a.y * b.x));
}
__device__ __forceinline__ float2 cadd(float2 a, float2 b) {
    return make_float2(a.x + b.x, a.y + b.y);
}
__device__ __forceinline__ float2 csub(float2 a, float2 b) {
    return make_float2(a.x - b.x, a.y - b.y);
}

// forward DIF radix-4 core (no twiddles): in/out in place
__device__ __forceinline__ void dif4(float2& x0, float2& x1, float2& x2, float2& x3) {
    float2 t02p = cadd(x0, x2), t02m = csub(x0, x2);
    float2 t13p = cadd(x1, x3), t13m = csub(x1, x3);
    float2 mi13 = make_float2(t13m.y, -t13m.x);       // -i*(x1-x3)
    x0 = cadd(t02p, t13p);
    x1 = cadd(t02m, mi13);
    x2 = csub(t02p, t13p);
    x3 = csub(t02m, mi13);
}

// inverse DIT radix-4 core (no twiddles)
__device__ __forceinline__ void dit4(float2& x0, float2& x1, float2& x2, float2& x3) {
    float2 s02p = cadd(x0, x2), s02m = csub(x0, x2);
    float2 s13p = cadd(x1, x3), s13m = csub(x1, x3);
    float2 pi13 = make_float2(-s13m.y, s13m.x);       // +i*(x1-x3)
    x0 = cadd(s02p, s13p);
    x1 = cadd(s02m, pi13);
    x2 = csub(s02p, s13p);
    x3 = csub(s02m, pi13);
}

extern "C" __global__ void __launch_bounds__(NTHR, 1)
fftconv_kernel(const float* __restrict__ xin,
               const float* __restrict__ hin,
               float* __restrict__ yout)
{
    extern __shared__ float2 sm[];
    float2* z  = sm;           // ZPAD float2 (padded data)
    float2* tw = sm + ZPAD;    // NFFT/4 twiddles

    const int tid = threadIdx.x;
    const size_t row = blockIdx.x;

    // ---- twiddles: tw[t] = exp(-2*pi*i*t/N), t in [0, N/4) ----
    {
        const float step = -6.28318530717958647692f / (float)NFFT;
        for (int t = tid; t < NFFT / 4; t += NTHR) {
            float s, c;
            __sincosf(step * (float)t, &s, &c);
            tw[t] = make_float2(c, s);
        }
    }

    // ---- load + pack ----
    {
        const float* xr = xin + row * LCONV;
        const float* hr = hin + row * LCONV;
        for (int i = tid; i < LCONV; i += NTHR)
            z[PADZ(i)] = make_float2(xr[i], hr[i]);
        for (int i = LCONV + tid; i < NFFT; i += NTHR)
            z[PADZ(i)] = make_float2(0.0f, 0.0f);
    }
    __syncthreads();

    // ---- forward: fused radix-16 stages (spans lm & lm-2), lm = 14, 10, 6 ----
    for (int lm = LOGN; lm >= 6; lm -= 4) {
        const int lq = lm - 4;
        const int qp = 1 << lq;        // q' (stride of second sub-stage)
        const int q  = qp << 2;        // q  (stride of first sub-stage)
        const int ts = LOGN - lm;
        #pragma unroll 1
        for (int g = tid; g < NFFT / 16; g += NTHR) {
            const int j    = g & (qp - 1);
            const int base = ((g >> lq) << lm) + j;
            float2 v[4][4];
            #pragma unroll
            for (int a = 0; a < 4; ++a)
                #pragma unroll
                for (int b = 0; b < 4; ++b)
                    v[a][b] = z[PADZ(base + a * q + b * qp)];
            // stage 1: DFT over a for each b, twiddle index (j + b*qp) << ts
            #pragma unroll
            for (int b = 0; b < 4; ++b) {
                float2 w1 = tw[(j + b * qp) << ts];
                float2 w2 = cmul(w1, w1);
                float2 w3 = cmul(w2, w1);
                dif4(v[0][b], v[1][b], v[2][b], v[3][b]);
                v[1][b] = cmul(v[1][b], w1);
                v[2][b] = cmul(v[2][b], w2);
                v[3][b] = cmul(v[3][b], w3);
            }
            // stage 2: DFT over b for each a, twiddle index j << (ts+2)
            {
                float2 w1 = tw[j << (ts + 2)];
                float2 w2 = cmul(w1, w1);
                float2 w3 = cmul(w2, w1);
                #pragma unroll
                for (int a = 0; a < 4; ++a) {
                    dif4(v[a][0], v[a][1], v[a][2], v[a][3]);
                    v[a][1] = cmul(v[a][1], w1);
                    v[a][2] = cmul(v[a][2], w2);
                    v[a][3] = cmul(v[a][3], w3);
                }
            }
            #pragma unroll
            for (int a = 0; a < 4; ++a)
                #pragma unroll
                for (int b = 0; b < 4; ++b)
                    z[PADZ(base + a * q + b * qp)] = v[a][b];
        }
        __syncthreads();
    }

    // ---- forward final radix-4 stage (lm = 2, q = 1, twiddles = 1) ----
    {
        #pragma unroll 1
        for (int g = tid; g < NFFT / 4; g += NTHR) {
            const int p = g << 2;
            float2 a0 = z[PADZ(p)], a1 = z[PADZ(p + 1)];
            float2 a2 = z[PADZ(p + 2)], a3 = z[PADZ(p + 3)];
            dif4(a0, a1, a2, a3);
            z[PADZ(p)] = a0; z[PADZ(p + 1)] = a1;
            z[PADZ(p + 2)] = a2; z[PADZ(p + 3)] = a3;
        }
        __syncthreads();
    }

    // ---- pointwise (addresses enumerated directly in digit-reversed domain) ----
    // Partner of address t = S4 + i   is 3*S4 + (S4-1-i)
    // Partner of address t = 2*S4 + i is 3*S4 - 1 - i      (i < S4/2)
    // Levels m = 14,12,...,2 touch disjoint address ranges [S4, 4*S4).
    if (tid == 0) {
        float2 z0 = z[0];                                   // k = 0
        z[0] = make_float2(z0.x * z0.y * SCALE_F, 0.0f);
        float2 zm = z[PADZ(2)];                             // k = N/2 (rev4 = 2)
        z[PADZ(2)] = make_float2(zm.x * zm.y * SCALE_F, 0.0f);
    }
    #pragma unroll 1
    for (int m = LOGN; m >= 2; m -= 2) {
        const int S4 = 1 << (m - 2);
        const int nl = S4 + (S4 >> 1);
        #pragma unroll 1
        for (int i = tid; i < nl; i += NTHR) {
            int t, tb;
            if (i < S4) { t = S4 + i;            tb = 3 * S4 + (S4 - 1 - i); }
            else        { int ii = i - S4; t = 2 * S4 + ii; tb = 3 * S4 - 1 - ii; }
            const int pa = PADZ(t), pb = PADZ(tb);
            float2 za = z[pa], zb = z[pb];
            float2 X = make_float2(0.5f * (za.x + zb.x), 0.5f * (za.y - zb.y));
            float2 d = make_float2(za.x - zb.x, za.y + zb.y);
            float2 H = make_float2(0.5f * d.y, -0.5f * d.x);
            float2 Y = cmul(X, H);
            Y.x *= SCALE_F; Y.y *= SCALE_F;
            z[pa] = Y;
            z[pb] = make_float2(Y.x, -Y.y);
        }
    }
    __syncthreads();

    // ---- inverse first radix-4 stage (lm = 2, twiddles = 1) ----
    {
        #pragma unroll 1
        for (int g = tid; g < NFFT / 4; g += NTHR) {
            const int p = g << 2;
            float2 c0 = z[PADZ(p)], c1 = z[PADZ(p + 1)];
            float2 c2 = z[PADZ(p + 2)], c3 = z[PADZ(p + 3)];
            dit4(c0, c1, c2, c3);
            z[PADZ(p)] = c0; z[PADZ(p + 1)] = c1;
            z[PADZ(p + 2)] = c2; z[PADZ(p + 3)] = c3;
        }
        __syncthreads();
    }

    // ---- inverse: fused radix-16 stages (spans lm_s & lm_s+2), lm_s = 4, 8, 12 ----
    for (int lm_s = 4; lm_s <= LOGN - 2; lm_s += 4) {
        const int lqs = lm_s - 2;
        const int qs  = 1 << lqs;      // stride of small-span stage
        const int ql  = 1 << lm_s;     // stride of large-span stage
        const int tss = LOGN - lm_s;
        #pragma unroll 1
        for (int g = tid; g < NFFT / 16; g += NTHR) {
            const int j    = g & (qs - 1);
            const int base = ((g >> lqs) << (lm_s + 2)) + j;
            float2 v[4][4];
            #pragma unroll
            for (int a = 0; a < 4; ++a)
                #pragma unroll
                for (int b = 0; b < 4; ++b)
                    v[a][b] = z[PADZ(base + a * qs + b * ql)];
            // small span: twiddle index j << tss (same for all b)
            {
                float2 wc = tw[j << tss];
                float2 w1 = make_float2(wc.x, -wc.y);     // conjugate
                float2 w2 = cmul(w1, w1);
                float2 w3 = cmul(w2, w1);
                #pragma unroll
                for (int b = 0; b < 4; ++b) {
                    v[1][b] = cmul(v[1][b], w1);
                    v[2][b] = cmul(v[2][b], w2);
                    v[3][b] = cmul(v[3][b], w3);
                    dit4(v[0][b], v[1][b], v[2][b], v[3][b]);
                }
            }
            // large span: twiddle index (j + a*qs) << (tss-2)
            #pragma unroll
            for (int a = 0; a < 4; ++a) {
                float2 wc = tw[(j + a * qs) << (tss - 2)];
                float2 w1 = make_float2(wc.x, -wc.y);
                float2 w2 = cmul(w1, w1);
                float2 w3 = cmul(w2, w1);
                v[a][1] = cmul(v[a][1], w1);
                v[a][2] = cmul(v[a][2], w2);
                v[a][3] = cmul(v[a][3], w3);
                dit4(v[a][0], v[a][1], v[a][2], v[a][3]);
            }
            #pragma unroll
            for (int a = 0; a < 4; ++a)
                #pragma unroll
                for (int b = 0; b < 4; ++b)
                    z[PADZ(base + a * qs + b * ql)] = v[a][b];
        }
        __syncthreads();
    }

    // ---- store real part of first L points ----
    {
        float* yr = yout + row * LCONV;
        for (int i = tid; i < LCONV; i += NTHR)
            yr[i] = z[PADZ(i)].x;
    }
}

extern "C" void kernel_launch(void* const* d_in, const int* in_sizes, int n_in,
                              void* d_out, int out_size) {
    const float* x = (const float*)d_in[0];
    const float* h = (const float*)d_in[1];
    float* y = (float*)d_out;

    const int B = in_sizes[0] / LCONV;
    const size_t smem_bytes = (size_t)(ZPAD + NFFT / 4) * sizeof(float2);  // 168 KB

    cudaFuncSetAttribute(fftconv_kernel,
                         cudaFuncAttributeMaxDynamicSharedMemorySize,
                         (int)smem_bytes);
    fftconv_kernel<<<B, NTHR, smem_bytes>>>(x, h, y);
}

// round 5
// speedup vs baseline: 2.3539x; 1.1251x over previous
#include <cuda_runtime.h>
#include <cuda_bf16.h>

// FFT long conv: y[b,:] = (1/N) * linear_conv(x[b], h[b])[:L], N = 2L = 16384.
// One CTA per row. z = x + i*h packing; fwd radix-4 DIF; Hermitian pointwise;
// inv radix-4 DIT. Round-4 (byte-identical resubmit; round-4 bench was a
// container infra failure, same signature as rounds 0/2, kernel never ran):
//  - NTHR 512 -> 1024 (occ 25% -> 50%; kernel was latency-bound at issue=43%)
//  - middle 3 passes (fwd lm=2, pointwise, inv lm=2) fused into ONE register
//    pass: pointwise partner of contiguous group [t..t+3] is [tb-3..tb] reversed,
//    so a thread does 8 points end-to-end. Saves 4 full-array smem round trips.

#define LCONV 8192
#define NFFT  16384
#define LOGN  14
#define NTHR  1024
#define SCALE_F (1.0f / ((float)NFFT * (float)NFFT))

#define PADZ(i) ((i) + ((i) >> 4))
#define ZPAD  (NFFT + (NFFT >> 4))     // 17408 float2

__device__ __forceinline__ float2 cmul(float2 a, float2 b) {
    return make_float2(fmaf(a.x, b.x, -a.y * b.y),
                       fmaf(a.x, b.y,  a.y * b.x));
}
__device__ __forceinline__ float2 cadd(float2 a, float2 b) {
    return make_float2(a.x + b.x, a.y + b.y);
}
__device__ __forceinline__ float2 csub(float2 a, float2 b) {
    return make_float2(a.x - b.x, a.y - b.y);
}

__device__ __forceinline__ void dif4(float2& x0, float2& x1, float2& x2, float2& x3) {
    float2 t02p = cadd(x0, x2), t02m = csub(x0, x2);
    float2 t13p = cadd(x1, x3), t13m = csub(x1, x3);
    float2 mi13 = make_float2(t13m.y, -t13m.x);       // -i*(x1-x3)
    x0 = cadd(t02p, t13p);
    x1 = cadd(t02m, mi13);
    x2 = csub(t02p, t13p);
    x3 = csub(t02m, mi13);
}

__device__ __forceinline__ void dit4(float2& x0, float2& x1, float2& x2, float2& x3) {
    float2 s02p = cadd(x0, x2), s02m = csub(x0, x2);
    float2 s13p = cadd(x1, x3), s13m = csub(x1, x3);
    float2 pi13 = make_float2(-s13m.y, s13m.x);       // +i*(x1-x3)
    x0 = cadd(s02p, s13p);
    x1 = cadd(s02m, pi13);
    x2 = csub(s02p, s13p);
    x3 = csub(s02m, pi13);
}

// pointwise unpack+multiply for a Hermitian pair; orientation-free
__device__ __forceinline__ void pw(float2& za, float2& zb) {
    float2 X = make_float2(0.5f * (za.x + zb.x), 0.5f * (za.y - zb.y));
    float2 d = make_float2(za.x - zb.x, za.y + zb.y);
    float2 H = make_float2(0.5f * d.y, -0.5f * d.x);
    float2 Y = cmul(X, H);
    Y.x *= SCALE_F; Y.y *= SCALE_F;
    za = Y;
    zb = make_float2(Y.x, -Y.y);
}

// one fused middle item: groups [ga..ga+3] and [gb..gb+3] (partner, reversed)
__device__ __forceinline__ void pair_item(float2* z, int ga, int gb) {
    float2 a0 = z[PADZ(ga)], a1 = z[PADZ(ga + 1)],
           a2 = z[PADZ(ga + 2)], a3 = z[PADZ(ga + 3)];
    float2 b0 = z[PADZ(gb)], b1 = z[PADZ(gb + 1)],
           b2 = z[PADZ(gb + 2)], b3 = z[PADZ(gb + 3)];
    dif4(a0, a1, a2, a3);
    dif4(b0, b1, b2, b3);
    pw(a0, b3); pw(a1, b2); pw(a2, b1); pw(a3, b0);
    dit4(a0, a1, a2, a3);
    dit4(b0, b1, b2, b3);
    z[PADZ(ga)] = a0; z[PADZ(ga + 1)] = a1;
    z[PADZ(ga + 2)] = a2; z[PADZ(ga + 3)] = a3;
    z[PADZ(gb)] = b0; z[PADZ(gb + 1)] = b1;
    z[PADZ(gb + 2)] = b2; z[PADZ(gb + 3)] = b3;
}

extern "C" __global__ void __launch_bounds__(NTHR, 1)
fftconv_kernel(const float* __restrict__ xin,
               const float* __restrict__ hin,
               float* __restrict__ yout)
{
    extern __shared__ float2 sm[];
    float2* z  = sm;           // ZPAD float2 (padded data)
    float2* tw = sm + ZPAD;    // NFFT/4 twiddles

    const int tid = threadIdx.x;
    const size_t row = blockIdx.x;

    // ---- twiddles: tw[t] = exp(-2*pi*i*t/N), t in [0, N/4) ----
    {
        const float step = -6.28318530717958647692f / (float)NFFT;
        for (int t = tid; t < NFFT / 4; t += NTHR) {
            float s, c;
            __sincosf(step * (float)t, &s, &c);
            tw[t] = make_float2(c, s);
        }
    }

    // ---- load + pack ----
    {
        const float* xr = xin + row * LCONV;
        const float* hr = hin + row * LCONV;
        for (int i = tid; i < LCONV; i += NTHR)
            z[PADZ(i)] = make_float2(xr[i], hr[i]);
        for (int i = LCONV + tid; i < NFFT; i += NTHR)
            z[PADZ(i)] = make_float2(0.0f, 0.0f);
    }
    __syncthreads();

    // ---- forward: fused radix-16 stages (spans lm & lm-2), lm = 14, 10, 6 ----
    for (int lm = LOGN; lm >= 6; lm -= 4) {
        const int lq = lm - 4;
        const int qp = 1 << lq;
        const int q  = qp << 2;
        const int ts = LOGN - lm;
        #pragma unroll 1
        for (int g = tid; g < NFFT / 16; g += NTHR) {
            const int j    = g & (qp - 1);
            const int base = ((g >> lq) << lm) + j;
            float2 v[4][4];
            #pragma unroll
            for (int a = 0; a < 4; ++a)
                #pragma unroll
                for (int b = 0; b < 4; ++b)
                    v[a][b] = z[PADZ(base + a * q + b * qp)];
            #pragma unroll
            for (int b = 0; b < 4; ++b) {
                float2 w1 = tw[(j + b * qp) << ts];
                float2 w2 = cmul(w1, w1);
                float2 w3 = cmul(w2, w1);
                dif4(v[0][b], v[1][b], v[2][b], v[3][b]);
                v[1][b] = cmul(v[1][b], w1);
                v[2][b] = cmul(v[2][b], w2);
                v[3][b] = cmul(v[3][b], w3);
            }
            {
                float2 w1 = tw[j << (ts + 2)];
                float2 w2 = cmul(w1, w1);
                float2 w3 = cmul(w2, w1);
                #pragma unroll
                for (int a = 0; a < 4; ++a) {
                    dif4(v[a][0], v[a][1], v[a][2], v[a][3]);
                    v[a][1] = cmul(v[a][1], w1);
                    v[a][2] = cmul(v[a][2], w2);
                    v[a][3] = cmul(v[a][3], w3);
                }
            }
            #pragma unroll
            for (int a = 0; a < 4; ++a)
                #pragma unroll
                for (int b = 0; b < 4; ++b)
                    z[PADZ(base + a * q + b * qp)] = v[a][b];
        }
        __syncthreads();
    }

    // ---- FUSED middle: fwd lm=2 radix-4 + pointwise + inv lm=2 radix-4 ----
    // group [t..t+3] pairs with [tb-3..tb] reversed; levels m=14..4 disjoint.
    {
        #pragma unroll 1
        for (int m = LOGN; m >= 4; m -= 2) {
            const int S4 = 1 << (m - 2);
            // branch 1: [S4, 2*S4) <-> [3*S4, 4*S4)
            #pragma unroll 1
            for (int it = tid; it < (S4 >> 2); it += NTHR)
                pair_item(z, S4 + 4 * it, 4 * S4 - 4 - 4 * it);
            // branch 2: [2*S4, 3*S4) pairs internally (needs >= 2 groups)
            if (S4 >= 16) {
                #pragma unroll 1
                for (int it = tid; it < (S4 >> 3); it += NTHR)
                    pair_item(z, 2 * S4 + 4 * it, 3 * S4 - 4 - 4 * it);
            }
        }
        // special: group [0..3] (selfs k=0 @0, k=N/2 @2; pair (1,3))
        if (tid == NTHR - 1) {
            float2 a0 = z[PADZ(0)], a1 = z[PADZ(1)],
                   a2 = z[PADZ(2)], a3 = z[PADZ(3)];
            dif4(a0, a1, a2, a3);
            a0 = make_float2(a0.x * a0.y * SCALE_F, 0.0f);
            a2 = make_float2(a2.x * a2.y * SCALE_F, 0.0f);
            pw(a1, a3);
            dit4(a0, a1, a2, a3);
            z[PADZ(0)] = a0; z[PADZ(1)] = a1;
            z[PADZ(2)] = a2; z[PADZ(3)] = a3;
        }
        // special: group [8..11] (S4=4 middle; pairs (8,11),(9,10))
        if (tid == NTHR - 2) {
            float2 a0 = z[PADZ(8)], a1 = z[PADZ(9)],
                   a2 = z[PADZ(10)], a3 = z[PADZ(11)];
            dif4(a0, a1, a2, a3);
            pw(a0, a3); pw(a1, a2);
            dit4(a0, a1, a2, a3);
            z[PADZ(8)] = a0; z[PADZ(9)] = a1;
            z[PADZ(10)] = a2; z[PADZ(11)] = a3;
        }
    }
    __syncthreads();

    // ---- inverse: fused radix-16 stages (spans lm_s & lm_s+2), lm_s = 4, 8, 12 ----
    for (int lm_s = 4; lm_s <= LOGN - 2; lm_s += 4) {
        const int lqs = lm_s - 2;
        const int qs  = 1 << lqs;
        const int ql  = 1 << lm_s;
        const int tss = LOGN - lm_s;
        #pragma unroll 1
        for (int g = tid; g < NFFT / 16; g += NTHR) {
            const int j    = g & (qs - 1);
            const int base = ((g >> lqs) << (lm_s + 2)) + j;
            float2 v[4][4];
            #pragma unroll
            for (int a = 0; a < 4; ++a)
                #pragma unroll
                for (int b = 0; b < 4; ++b)
                    v[a][b] = z[PADZ(base + a * qs + b * ql)];
            {
                float2 wc = tw[j << tss];
                float2 w1 = make_float2(wc.x, -wc.y);
                float2 w2 = cmul(w1, w1);
                float2 w3 = cmul(w2, w1);
                #pragma unroll
                for (int b = 0; b < 4; ++b) {
                    v[1][b] = cmul(v[1][b], w1);
                    v[2][b] = cmul(v[2][b], w2);
                    v[3][b] = cmul(v[3][b], w3);
                    dit4(v[0][b], v[1][b], v[2][b], v[3][b]);
                }
            }
            #pragma unroll
            for (int a = 0; a < 4; ++a) {
                float2 wc = tw[(j + a * qs) << (tss - 2)];
                float2 w1 = make_float2(wc.x, -wc.y);
                float2 w2 = cmul(w1, w1);
                float2 w3 = cmul(w2, w1);
                v[a][1] = cmul(v[a][1], w1);
                v[a][2] = cmul(v[a][2], w2);
                v[a][3] = cmul(v[a][3], w3);
                dit4(v[a][0], v[a][1], v[a][2], v[a][3]);
            }
            #pragma unroll
            for (int a = 0; a < 4; ++a)
                #pragma unroll
                for (int b = 0; b < 4; ++b)
                    z[PADZ(base + a * qs + b * ql)] = v[a][b];
        }
        __syncthreads();
    }

    // ---- store real part of first L points ----
    {
        float* yr = yout + row * LCONV;
        for (int i = tid; i < LCONV; i += NTHR)
            yr[i] = z[PADZ(i)].x;
    }
}

extern "C" void kernel_launch(void* const* d_in, const int* in_sizes, int n_in,
                              void* d_out, int out_size) {
    const float* x = (const float*)d_in[0];
    const float* h = (const float*)d_in[1];
    float* y = (float*)d_out;

    const int B = in_sizes[0] / LCONV;
    const size_t smem_bytes = (size_t)(ZPAD + NFFT / 4) * sizeof(float2);  // 168 KB

    cudaFuncSetAttribute(fftconv_kernel,
                         cudaFuncAttributeMaxDynamicSharedMemorySize,
                         (int)smem_bytes);
    fftconv_kernel<<<B, NTHR, smem_bytes>>>(x, h, y);
}

// round 6
// speedup vs baseline: 3.1045x; 1.3189x over previous
#include <cuda_runtime.h>
#include <cuda_bf16.h>

// FFT long conv: y[b,:] = (1/N) * linear_conv(x[b], h[b])[:L], N = 2L = 16384.
// One CTA per row, 1024 threads, one radix-16 item per thread per stage.
// Round-6:
//  - fwd stage 1 fused with gmem load; zero upper half exploited (degenerate
//    radix-4); pack + zero-fill passes and one barrier deleted.
//  - last inverse stage fused with gmem store; only the b∈{0,1} real outputs
//    computed; final smem stores + readout pass + one barrier deleted.

#define LCONV 8192
#define NFFT  16384
#define LOGN  14
#define NTHR  1024
#define SCALE_F (1.0f / ((float)NFFT * (float)NFFT))

#define PADZ(i) ((i) + ((i) >> 4))
#define ZPAD  (NFFT + (NFFT >> 4))     // 17408 float2

__device__ __forceinline__ float2 cmul(float2 a, float2 b) {
    return make_float2(fmaf(a.x, b.x, -a.y * b.y),
                       fmaf(a.x, b.y,  a.y * b.x));
}
__device__ __forceinline__ float2 cadd(float2 a, float2 b) {
    return make_float2(a.x + b.x, a.y + b.y);
}
__device__ __forceinline__ float2 csub(float2 a, float2 b) {
    return make_float2(a.x - b.x, a.y - b.y);
}

__device__ __forceinline__ void dif4(float2& x0, float2& x1, float2& x2, float2& x3) {
    float2 t02p = cadd(x0, x2), t02m = csub(x0, x2);
    float2 t13p = cadd(x1, x3), t13m = csub(x1, x3);
    float2 mi13 = make_float2(t13m.y, -t13m.x);       // -i*(x1-x3)
    x0 = cadd(t02p, t13p);
    x1 = cadd(t02m, mi13);
    x2 = csub(t02p, t13p);
    x3 = csub(t02m, mi13);
}

__device__ __forceinline__ void dit4(float2& x0, float2& x1, float2& x2, float2& x3) {
    float2 s02p = cadd(x0, x2), s02m = csub(x0, x2);
    float2 s13p = cadd(x1, x3), s13m = csub(x1, x3);
    float2 pi13 = make_float2(-s13m.y, s13m.x);       // +i*(x1-x3)
    x0 = cadd(s02p, s13p);
    x1 = cadd(s02m, pi13);
    x2 = csub(s02p, s13p);
    x3 = csub(s02m, pi13);
}

// pointwise unpack+multiply for a Hermitian pair; orientation-free
__device__ __forceinline__ void pw(float2& za, float2& zb) {
    float2 X = make_float2(0.5f * (za.x + zb.x), 0.5f * (za.y - zb.y));
    float2 d = make_float2(za.x - zb.x, za.y + zb.y);
    float2 H = make_float2(0.5f * d.y, -0.5f * d.x);
    float2 Y = cmul(X, H);
    Y.x *= SCALE_F; Y.y *= SCALE_F;
    za = Y;
    zb = make_float2(Y.x, -Y.y);
}

// one fused middle item: groups [ga..ga+3] and [gb..gb+3] (partner, reversed)
__device__ __forceinline__ void pair_item(float2* z, int ga, int gb) {
    float2 a0 = z[PADZ(ga)], a1 = z[PADZ(ga + 1)],
           a2 = z[PADZ(ga + 2)], a3 = z[PADZ(ga + 3)];
    float2 b0 = z[PADZ(gb)], b1 = z[PADZ(gb + 1)],
           b2 = z[PADZ(gb + 2)], b3 = z[PADZ(gb + 3)];
    dif4(a0, a1, a2, a3);
    dif4(b0, b1, b2, b3);
    pw(a0, b3); pw(a1, b2); pw(a2, b1); pw(a3, b0);
    dit4(a0, a1, a2, a3);
    dit4(b0, b1, b2, b3);
    z[PADZ(ga)] = a0; z[PADZ(ga + 1)] = a1;
    z[PADZ(ga + 2)] = a2; z[PADZ(ga + 3)] = a3;
    z[PADZ(gb)] = b0; z[PADZ(gb + 1)] = b1;
    z[PADZ(gb + 2)] = b2; z[PADZ(gb + 3)] = b3;
}

extern "C" __global__ void __launch_bounds__(NTHR, 1)
fftconv_kernel(const float* __restrict__ xin,
               const float* __restrict__ hin,
               float* __restrict__ yout)
{
    extern __shared__ float2 sm[];
    float2* z  = sm;           // ZPAD float2 (padded data)
    float2* tw = sm + ZPAD;    // NFFT/4 twiddles

    const int tid = threadIdx.x;
    const size_t row = blockIdx.x;
    const float* xr = xin + row * LCONV;
    const float* hr = hin + row * LCONV;
    float* yr = yout + row * LCONV;

    // ---- stage-1 gmem loads, issued early so LDG hides under sincos ----
    float2 in0[4], in1[4];
    #pragma unroll
    for (int b = 0; b < 4; ++b) {
        const int i0 = tid + (b << 10);
        in0[b] = make_float2(xr[i0], hr[i0]);
        const int i1 = i0 + 4096;
        in1[b] = make_float2(xr[i1], hr[i1]);
    }

    // ---- twiddles: tw[t] = exp(-2*pi*i*t/N), t in [0, N/4) ----
    {
        const float step = -6.28318530717958647692f / (float)NFFT;
        #pragma unroll
        for (int t = tid; t < NFFT / 4; t += NTHR) {
            float s, c;
            __sincosf(step * (float)t, &s, &c);
            tw[t] = make_float2(c, s);
        }
    }
    __syncthreads();

    // ---- fwd stage lm=14, fused with input; indices >= 8192 are zero ----
    {
        const int j = tid;
        float2 v[4][4];
        #pragma unroll
        for (int b = 0; b < 4; ++b) {
            float2 x0 = in0[b], x1 = in1[b];
            float2 w1 = tw[j + (b << 10)];
            float2 w2 = cmul(w1, w1);
            float2 w3 = cmul(w2, w1);
            v[0][b] = cadd(x0, x1);
            v[1][b] = cmul(make_float2(x0.x + x1.y, x0.y - x1.x), w1); // x0 - i*x1
            v[2][b] = cmul(csub(x0, x1), w2);
            v[3][b] = cmul(make_float2(x0.x - x1.y, x0.y + x1.x), w3); // x0 + i*x1
        }
        float2 w1 = tw[j << 2];
        float2 w2 = cmul(w1, w1);
        float2 w3 = cmul(w2, w1);
        #pragma unroll
        for (int a = 0; a < 4; ++a) {
            dif4(v[a][0], v[a][1], v[a][2], v[a][3]);
            v[a][1] = cmul(v[a][1], w1);
            v[a][2] = cmul(v[a][2], w2);
            v[a][3] = cmul(v[a][3], w3);
        }
        #pragma unroll
        for (int a = 0; a < 4; ++a)
            #pragma unroll
            for (int b = 0; b < 4; ++b)
                z[PADZ(j + a * 4096 + (b << 10))] = v[a][b];
    }
    __syncthreads();

    // ---- fwd stages lm = 10, 6 (generic fused radix-16) ----
    #pragma unroll 1
    for (int lm = 10; lm >= 6; lm -= 4) {
        const int lq = lm - 4;
        const int qp = 1 << lq;
        const int q  = qp << 2;
        const int ts = LOGN - lm;
        const int g  = tid;
        const int j    = g & (qp - 1);
        const int base = ((g >> lq) << lm) + j;
        float2 v[4][4];
        #pragma unroll
        for (int a = 0; a < 4; ++a)
            #pragma unroll
            for (int b = 0; b < 4; ++b)
                v[a][b] = z[PADZ(base + a * q + b * qp)];
        #pragma unroll
        for (int b = 0; b < 4; ++b) {
            float2 w1 = tw[(j + b * qp) << ts];
            float2 w2 = cmul(w1, w1);
            float2 w3 = cmul(w2, w1);
            dif4(v[0][b], v[1][b], v[2][b], v[3][b]);
            v[1][b] = cmul(v[1][b], w1);
            v[2][b] = cmul(v[2][b], w2);
            v[3][b] = cmul(v[3][b], w3);
        }
        {
            float2 w1 = tw[j << (ts + 2)];
            float2 w2 = cmul(w1, w1);
            float2 w3 = cmul(w2, w1);
            #pragma unroll
            for (int a = 0; a < 4; ++a) {
                dif4(v[a][0], v[a][1], v[a][2], v[a][3]);
                v[a][1] = cmul(v[a][1], w1);
                v[a][2] = cmul(v[a][2], w2);
                v[a][3] = cmul(v[a][3], w3);
            }
        }
        #pragma unroll
        for (int a = 0; a < 4; ++a)
            #pragma unroll
            for (int b = 0; b < 4; ++b)
                z[PADZ(base + a * q + b * qp)] = v[a][b];
        __syncthreads();
    }

    // ---- FUSED middle: fwd lm=2 radix-4 + pointwise + inv lm=2 radix-4 ----
    {
        #pragma unroll 1
        for (int m = LOGN; m >= 4; m -= 2) {
            const int S4 = 1 << (m - 2);
            // branch 1: [S4, 2*S4) <-> [3*S4, 4*S4)
            #pragma unroll 1
            for (int it = tid; it < (S4 >> 2); it += NTHR)
                pair_item(z, S4 + 4 * it, 4 * S4 - 4 - 4 * it);
            // branch 2: [2*S4, 3*S4) pairs internally (needs >= 2 groups)
            if (S4 >= 16) {
                #pragma unroll 1
                for (int it = tid; it < (S4 >> 3); it += NTHR)
                    pair_item(z, 2 * S4 + 4 * it, 3 * S4 - 4 - 4 * it);
            }
        }
        // special: group [0..3] (selfs k=0 @0, k=N/2 @2; pair (1,3))
        if (tid == NTHR - 1) {
            float2 a0 = z[PADZ(0)], a1 = z[PADZ(1)],
                   a2 = z[PADZ(2)], a3 = z[PADZ(3)];
            dif4(a0, a1, a2, a3);
            a0 = make_float2(a0.x * a0.y * SCALE_F, 0.0f);
            a2 = make_float2(a2.x * a2.y * SCALE_F, 0.0f);
            pw(a1, a3);
            dit4(a0, a1, a2, a3);
            z[PADZ(0)] = a0; z[PADZ(1)] = a1;
            z[PADZ(2)] = a2; z[PADZ(3)] = a3;
        }
        // special: group [8..11] (S4=4 middle; pairs (8,11),(9,10))
        if (tid == NTHR - 2) {
            float2 a0 = z[PADZ(8)], a1 = z[PADZ(9)],
                   a2 = z[PADZ(10)], a3 = z[PADZ(11)];
            dif4(a0, a1, a2, a3);
            pw(a0, a3); pw(a1, a2);
            dit4(a0, a1, a2, a3);
            z[PADZ(8)] = a0; z[PADZ(9)] = a1;
            z[PADZ(10)] = a2; z[PADZ(11)] = a3;
        }
    }
    __syncthreads();

    // ---- inverse stages lm_s = 4, 8 (generic fused radix-16) ----
    #pragma unroll 1
    for (int lm_s = 4; lm_s <= 8; lm_s += 4) {
        const int lqs = lm_s - 2;
        const int qs  = 1 << lqs;
        const int ql  = 1 << lm_s;
        const int tss = LOGN - lm_s;
        const int g   = tid;
        const int j    = g & (qs - 1);
        const int base = ((g >> lqs) << (lm_s + 2)) + j;
        float2 v[4][4];
        #pragma unroll
        for (int a = 0; a < 4; ++a)
            #pragma unroll
            for (int b = 0; b < 4; ++b)
                v[a][b] = z[PADZ(base + a * qs + b * ql)];
        {
            float2 wc = tw[j << tss];
            float2 w1 = make_float2(wc.x, -wc.y);
            float2 w2 = cmul(w1, w1);
            float2 w3 = cmul(w2, w1);
            #pragma unroll
            for (int b = 0; b < 4; ++b) {
                v[1][b] = cmul(v[1][b], w1);
                v[2][b] = cmul(v[2][b], w2);
                v[3][b] = cmul(v[3][b], w3);
                dit4(v[0][b], v[1][b], v[2][b], v[3][b]);
            }
        }
        #pragma unroll
        for (int a = 0; a < 4; ++a) {
            float2 wc = tw[(j + a * qs) << (tss - 2)];
            float2 w1 = make_float2(wc.x, -wc.y);
            float2 w2 = cmul(w1, w1);
            float2 w3 = cmul(w2, w1);
            v[a][1] = cmul(v[a][1], w1);
            v[a][2] = cmul(v[a][2], w2);
            v[a][3] = cmul(v[a][3], w3);
            dit4(v[a][0], v[a][1], v[a][2], v[a][3]);
        }
        #pragma unroll
        for (int a = 0; a < 4; ++a)
            #pragma unroll
            for (int b = 0; b < 4; ++b)
                z[PADZ(base + a * qs + b * ql)] = v[a][b];
        __syncthreads();
    }

    // ---- inverse stage lm_s = 12, fused with gmem store ----
    // outputs at j + 1024*a + 4096*b; b in {0,1} covers [0, 8192) exactly.
    {
        const int j = tid;       // qs = 1024, ql = 4096, tss = 2
        float2 v[4][4];
        #pragma unroll
        for (int a = 0; a < 4; ++a)
            #pragma unroll
            for (int b = 0; b < 4; ++b)
                v[a][b] = z[PADZ(j + (a << 10) + (b << 12))];
        {
            float2 wc = tw[j << 2];
            float2 w1 = make_float2(wc.x, -wc.y);
            float2 w2 = cmul(w1, w1);
            float2 w3 = cmul(w2, w1);
            #pragma unroll
            for (int b = 0; b < 4; ++b) {
                v[1][b] = cmul(v[1][b], w1);
                v[2][b] = cmul(v[2][b], w2);
                v[3][b] = cmul(v[3][b], w3);
                dit4(v[0][b], v[1][b], v[2][b], v[3][b]);
            }
        }
        #pragma unroll
        for (int a = 0; a < 4; ++a) {
            float2 wc = tw[j + (a << 10)];
            float2 w1 = make_float2(wc.x, -wc.y);
            float2 w2 = cmul(w1, w1);
            float2 w3 = cmul(w2, w1);
            float2 c0 = v[a][0];
            float2 c1 = cmul(v[a][1], w1);
            float  c2x = fmaf(v[a][2].x, w2.x, -v[a][2].y * w2.y);  // Re only
            float2 c3 = cmul(v[a][3], w3);
            // b=0: Re(s02p + s13p); b=1: Re(s02m + i*(c1-c3))
            float y0 = (c0.x + c2x) + (c1.x + c3.x);
            float y1 = (c0.x - c2x) - (c1.y - c3.y);
            yr[j + (a << 10)]        = y0;
            yr[j + (a << 10) + 4096] = y1;
        }
    }
}

extern "C" void kernel_launch(void* const* d_in, const int* in_sizes, int n_in,
                              void* d_out, int out_size) {
    const float* x = (const float*)d_in[0];
    const float* h = (const float*)d_in[1];
    float* y = (float*)d_out;

    const int B = in_sizes[0] / LCONV;
    const size_t smem_bytes = (size_t)(ZPAD + NFFT / 4) * sizeof(float2);  // 168 KB

    cudaFuncSetAttribute(fftconv_kernel,
                         cudaFuncAttributeMaxDynamicSharedMemorySize,
                         (int)smem_bytes);
    fftconv_kernel<<<B, NTHR, smem_bytes>>>(x, h, y);
}

// round 7
// speedup vs baseline: 3.4314x; 1.1053x over previous
#include <cuda_runtime.h>
#include <cuda_bf16.h>

// FFT long conv: y[b,:] = (1/N) * linear_conv(x[b], h[b])[:L], N = 2L = 16384.
// One CTA per row, 1024 threads, one radix-16 item per thread per stage.
// Round-7: all smem addressing rewritten as PADZ(base) + compile-time padded
// offset (valid because base%16 + off%16 < 16 in every stage, so the pad term
// splits exactly). Stages templated on LM so offsets become LDS/STS immediates,
// deleting most of the ALU-pipe address math.

#define LCONV 8192
#define NFFT  16384
#define LOGN  14
#define NTHR  1024
#define SCALE_F (1.0f / ((float)NFFT * (float)NFFT))

#define PADZ(i) ((i) + ((i) >> 4))
#define ZPAD  (NFFT + (NFFT >> 4))     // 17408 float2

__device__ __forceinline__ float2 cmul(float2 a, float2 b) {
    return make_float2(fmaf(a.x, b.x, -a.y * b.y),
                       fmaf(a.x, b.y,  a.y * b.x));
}
__device__ __forceinline__ float2 cadd(float2 a, float2 b) {
    return make_float2(a.x + b.x, a.y + b.y);
}
__device__ __forceinline__ float2 csub(float2 a, float2 b) {
    return make_float2(a.x - b.x, a.y - b.y);
}

__device__ __forceinline__ void dif4(float2& x0, float2& x1, float2& x2, float2& x3) {
    float2 t02p = cadd(x0, x2), t02m = csub(x0, x2);
    float2 t13p = cadd(x1, x3), t13m = csub(x1, x3);
    float2 mi13 = make_float2(t13m.y, -t13m.x);       // -i*(x1-x3)
    x0 = cadd(t02p, t13p);
    x1 = cadd(t02m, mi13);
    x2 = csub(t02p, t13p);
    x3 = csub(t02m, mi13);
}

__device__ __forceinline__ void dit4(float2& x0, float2& x1, float2& x2, float2& x3) {
    float2 s02p = cadd(x0, x2), s02m = csub(x0, x2);
    float2 s13p = cadd(x1, x3), s13m = csub(x1, x3);
    float2 pi13 = make_float2(-s13m.y, s13m.x);       // +i*(x1-x3)
    x0 = cadd(s02p, s13p);
    x1 = cadd(s02m, pi13);
    x2 = csub(s02p, s13p);
    x3 = csub(s02m, pi13);
}

// pointwise unpack+multiply for a Hermitian pair; orientation-free
__device__ __forceinline__ void pw(float2& za, float2& zb) {
    float2 X = make_float2(0.5f * (za.x + zb.x), 0.5f * (za.y - zb.y));
    float2 d = make_float2(za.x - zb.x, za.y + zb.y);
    float2 H = make_float2(0.5f * d.y, -0.5f * d.x);
    float2 Y = cmul(X, H);
    Y.x *= SCALE_F; Y.y *= SCALE_F;
    za = Y;
    zb = make_float2(Y.x, -Y.y);
}

// one fused middle item; pga/pgb are PRE-PADDED base addresses (offsets 0..3
// need no pad correction: base%16 in {0,4,8,12}, off<=3 -> no carry)
__device__ __forceinline__ void pair_item(float2* z, int pga, int pgb) {
    float2 a0 = z[pga], a1 = z[pga + 1], a2 = z[pga + 2], a3 = z[pga + 3];
    float2 b0 = z[pgb], b1 = z[pgb + 1], b2 = z[pgb + 2], b3 = z[pgb + 3];
    dif4(a0, a1, a2, a3);
    dif4(b0, b1, b2, b3);
    pw(a0, b3); pw(a1, b2); pw(a2, b1); pw(a3, b0);
    dit4(a0, a1, a2, a3);
    dit4(b0, b1, b2, b3);
    z[pga] = a0; z[pga + 1] = a1; z[pga + 2] = a2; z[pga + 3] = a3;
    z[pgb] = b0; z[pgb + 1] = b1; z[pgb + 2] = b2; z[pgb + 3] = b3;
}

// generic fused fwd radix-16 stage (spans LM and LM-2), compile-time LM
template<int LM>
__device__ __forceinline__ void fwd16(float2* __restrict__ z,
                                      const float2* __restrict__ tw, int tid) {
    constexpr int LQ = LM - 4;
    constexpr int QP = 1 << LQ;
    constexpr int Q  = QP << 2;
    constexpr int TS = LOGN - LM;
    const int j    = tid & (QP - 1);
    const int base = ((tid >> LQ) << LM) + j;
    const int pb   = PADZ(base);
    float2 v[4][4];
    #pragma unroll
    for (int a = 0; a < 4; ++a)
        #pragma unroll
        for (int b = 0; b < 4; ++b) {
            const int off = a * Q + b * QP;          // compile-time
            v[a][b] = z[pb + off + (off >> 4)];
        }
    #pragma unroll
    for (int b = 0; b < 4; ++b) {
        float2 w1 = tw[(j + b * QP) << TS];
        float2 w2 = cmul(w1, w1);
        float2 w3 = cmul(w2, w1);
        dif4(v[0][b], v[1][b], v[2][b], v[3][b]);
        v[1][b] = cmul(v[1][b], w1);
        v[2][b] = cmul(v[2][b], w2);
        v[3][b] = cmul(v[3][b], w3);
    }
    {
        float2 w1 = tw[j << (TS + 2)];
        float2 w2 = cmul(w1, w1);
        float2 w3 = cmul(w2, w1);
        #pragma unroll
        for (int a = 0; a < 4; ++a) {
            dif4(v[a][0], v[a][1], v[a][2], v[a][3]);
            v[a][1] = cmul(v[a][1], w1);
            v[a][2] = cmul(v[a][2], w2);
            v[a][3] = cmul(v[a][3], w3);
        }
    }
    #pragma unroll
    for (int a = 0; a < 4; ++a)
        #pragma unroll
        for (int b = 0; b < 4; ++b) {
            const int off = a * Q + b * QP;
            z[pb + off + (off >> 4)] = v[a][b];
        }
}

// generic fused inverse radix-16 stage (spans LMS and LMS+2), compile-time LMS
template<int LMS>
__device__ __forceinline__ void inv16(float2* __restrict__ z,
                                      const float2* __restrict__ tw, int tid) {
    constexpr int LQS = LMS - 2;
    constexpr int QS  = 1 << LQS;
    constexpr int QL  = 1 << LMS;
    constexpr int TSS = LOGN - LMS;
    const int j    = tid & (QS - 1);
    const int base = ((tid >> LQS) << (LMS + 2)) + j;
    const int pb   = PADZ(base);
    float2 v[4][4];
    #pragma unroll
    for (int a = 0; a < 4; ++a)
        #pragma unroll
        for (int b = 0; b < 4; ++b) {
            const int off = a * QS + b * QL;
            v[a][b] = z[pb + off + (off >> 4)];
        }
    {
        float2 wc = tw[j << TSS];
        float2 w1 = make_float2(wc.x, -wc.y);
        float2 w2 = cmul(w1, w1);
        float2 w3 = cmul(w2, w1);
        #pragma unroll
        for (int b = 0; b < 4; ++b) {
            v[1][b] = cmul(v[1][b], w1);
            v[2][b] = cmul(v[2][b], w2);
            v[3][b] = cmul(v[3][b], w3);
            dit4(v[0][b], v[1][b], v[2][b], v[3][b]);
        }
    }
    #pragma unroll
    for (int a = 0; a < 4; ++a) {
        float2 wc = tw[(j + a * QS) << (TSS - 2)];
        float2 w1 = make_float2(wc.x, -wc.y);
        float2 w2 = cmul(w1, w1);
        float2 w3 = cmul(w2, w1);
        v[a][1] = cmul(v[a][1], w1);
        v[a][2] = cmul(v[a][2], w2);
        v[a][3] = cmul(v[a][3], w3);
        dit4(v[a][0], v[a][1], v[a][2], v[a][3]);
    }
    #pragma unroll
    for (int a = 0; a < 4; ++a)
        #pragma unroll
        for (int b = 0; b < 4; ++b) {
            const int off = a * QS + b * QL;
            z[pb + off + (off >> 4)] = v[a][b];
        }
}

extern "C" __global__ void __launch_bounds__(NTHR, 1)
fftconv_kernel(const float* __restrict__ xin,
               const float* __restrict__ hin,
               float* __restrict__ yout)
{
    extern __shared__ float2 sm[];
    float2* z  = sm;           // ZPAD float2 (padded data)
    float2* tw = sm + ZPAD;    // NFFT/4 twiddles

    const int tid = threadIdx.x;
    const size_t row = blockIdx.x;
    const float* xr = xin + row * LCONV;
    const float* hr = hin + row * LCONV;
    float* yr = yout + row * LCONV;

    // ---- stage-1 gmem loads, issued early so LDG hides under sincos ----
    float2 in0[4], in1[4];
    #pragma unroll
    for (int b = 0; b < 4; ++b) {
        const int i0 = tid + (b << 10);
        in0[b] = make_float2(xr[i0], hr[i0]);
        const int i1 = i0 + 4096;
        in1[b] = make_float2(xr[i1], hr[i1]);
    }

    // ---- twiddles: tw[t] = exp(-2*pi*i*t/N), t in [0, N/4) ----
    {
        const float step = -6.28318530717958647692f / (float)NFFT;
        #pragma unroll
        for (int t = tid; t < NFFT / 4; t += NTHR) {
            float s, c;
            __sincosf(step * (float)t, &s, &c);
            tw[t] = make_float2(c, s);
        }
    }
    __syncthreads();

    // ---- fwd stage lm=14, fused with input; indices >= 8192 are zero ----
    {
        const int j  = tid;
        const int pb = PADZ(j);
        float2 v[4][4];
        #pragma unroll
        for (int b = 0; b < 4; ++b) {
            float2 x0 = in0[b], x1 = in1[b];
            float2 w1 = tw[j + (b << 10)];
            float2 w2 = cmul(w1, w1);
            float2 w3 = cmul(w2, w1);
            v[0][b] = cadd(x0, x1);
            v[1][b] = cmul(make_float2(x0.x + x1.y, x0.y - x1.x), w1); // x0 - i*x1
            v[2][b] = cmul(csub(x0, x1), w2);
            v[3][b] = cmul(make_float2(x0.x - x1.y, x0.y + x1.x), w3); // x0 + i*x1
        }
        float2 w1 = tw[j << 2];
        float2 w2 = cmul(w1, w1);
        float2 w3 = cmul(w2, w1);
        #pragma unroll
        for (int a = 0; a < 4; ++a) {
            dif4(v[a][0], v[a][1], v[a][2], v[a][3]);
            v[a][1] = cmul(v[a][1], w1);
            v[a][2] = cmul(v[a][2], w2);
            v[a][3] = cmul(v[a][3], w3);
        }
        #pragma unroll
        for (int a = 0; a < 4; ++a)
            #pragma unroll
            for (int b = 0; b < 4; ++b) {
                const int off = a * 4096 + b * 1024;
                z[pb + off + (off >> 4)] = v[a][b];
            }
    }
    __syncthreads();

    // ---- fwd stages lm = 10, 6 ----
    fwd16<10>(z, tw, tid);
    __syncthreads();
    fwd16<6>(z, tw, tid);
    __syncthreads();

    // ---- FUSED middle: fwd lm=2 radix-4 + pointwise + inv lm=2 radix-4 ----
    {
        #pragma unroll 1
        for (int m = LOGN; m >= 4; m -= 2) {
            const int S4 = 1 << (m - 2);
            // branch 1: [S4, 2*S4) <-> [3*S4, 4*S4)
            #pragma unroll 1
            for (int it = tid; it < (S4 >> 2); it += NTHR) {
                const int ga = S4 + 4 * it;
                const int gb = 4 * S4 - 4 - 4 * it;
                pair_item(z, PADZ(ga), PADZ(gb));
            }
            // branch 2: [2*S4, 3*S4) pairs internally (needs >= 2 groups)
            if (S4 >= 16) {
                #pragma unroll 1
                for (int it = tid; it < (S4 >> 3); it += NTHR) {
                    const int ga = 2 * S4 + 4 * it;
                    const int gb = 3 * S4 - 4 - 4 * it;
                    pair_item(z, PADZ(ga), PADZ(gb));
                }
            }
        }
        // special: group [0..3] (selfs k=0 @0, k=N/2 @2; pair (1,3))
        if (tid == NTHR - 1) {
            float2 a0 = z[0], a1 = z[1], a2 = z[2], a3 = z[3];
            dif4(a0, a1, a2, a3);
            a0 = make_float2(a0.x * a0.y * SCALE_F, 0.0f);
            a2 = make_float2(a2.x * a2.y * SCALE_F, 0.0f);
            pw(a1, a3);
            dit4(a0, a1, a2, a3);
            z[0] = a0; z[1] = a1; z[2] = a2; z[3] = a3;
        }
        // special: group [8..11] (S4=4 middle; pairs (8,11),(9,10))
        if (tid == NTHR - 2) {
            float2 a0 = z[8], a1 = z[9], a2 = z[10], a3 = z[11];
            dif4(a0, a1, a2, a3);
            pw(a0, a3); pw(a1, a2);
            dit4(a0, a1, a2, a3);
            z[8] = a0; z[9] = a1; z[10] = a2; z[11] = a3;
        }
    }
    __syncthreads();

    // ---- inverse stages lm_s = 4, 8 ----
    inv16<4>(z, tw, tid);
    __syncthreads();
    inv16<8>(z, tw, tid);
    __syncthreads();

    // ---- inverse stage lm_s = 12, fused with gmem store ----
    // outputs at j + 1024*a + 4096*b; b in {0,1} covers [0, 8192) exactly.
    {
        const int j  = tid;      // qs = 1024, ql = 4096, tss = 2
        const int pb = PADZ(j);
        float2 v[4][4];
        #pragma unroll
        for (int a = 0; a < 4; ++a)
            #pragma unroll
            for (int b = 0; b < 4; ++b) {
                const int off = (a << 10) + (b << 12);
                v[a][b] = z[pb + off + (off >> 4)];
            }
        {
            float2 wc = tw[j << 2];
            float2 w1 = make_float2(wc.x, -wc.y);
            float2 w2 = cmul(w1, w1);
            float2 w3 = cmul(w2, w1);
            #pragma unroll
            for (int b = 0; b < 4; ++b) {
                v[1][b] = cmul(v[1][b], w1);
                v[2][b] = cmul(v[2][b], w2);
                v[3][b] = cmul(v[3][b], w3);
                dit4(v[0][b], v[1][b], v[2][b], v[3][b]);
            }
        }
        #pragma unroll
        for (int a = 0; a < 4; ++a) {
            float2 wc = tw[j + (a << 10)];
            float2 w1 = make_float2(wc.x, -wc.y);
            float2 w2 = cmul(w1, w1);
            float2 w3 = cmul(w2, w1);
            float2 c0 = v[a][0];
            float2 c1 = cmul(v[a][1], w1);
            float  c2x = fmaf(v[a][2].x, w2.x, -v[a][2].y * w2.y);  // Re only
            float2 c3 = cmul(v[a][3], w3);
            // b=0: Re(s02p + s13p); b=1: Re(s02m + i*(c1-c3))
            float y0 = (c0.x + c2x) + (c1.x + c3.x);
            float y1 = (c0.x - c2x) - (c1.y - c3.y);
            yr[j + (a << 10)]        = y0;
            yr[j + (a << 10) + 4096] = y1;
        }
    }
}

extern "C" void kernel_launch(void* const* d_in, const int* in_sizes, int n_in,
                              void* d_out, int out_size) {
    const float* x = (const float*)d_in[0];
    const float* h = (const float*)d_in[1];
    float* y = (float*)d_out;

    const int B = in_sizes[0] / LCONV;
    const size_t smem_bytes = (size_t)(ZPAD + NFFT / 4) * sizeof(float2);  // 168 KB

    cudaFuncSetAttribute(fftconv_kernel,
                         cudaFuncAttributeMaxDynamicSharedMemorySize,
                         (int)smem_bytes);
    fftconv_kernel<<<B, NTHR, smem_bytes>>>(x, h, y);
}

// round 8
// speedup vs baseline: 4.5504x; 1.3261x over previous
#include <cuda_runtime.h>
#include <cuda_bf16.h>

// FFT long conv: y[b,:] = (1/N) * linear_conv(x[b], h[b])[:L], N = 2L = 16384.
// One CTA per row, 1024 threads, one radix-16 item per thread per stage.
// Round-8: twiddle table gets its own two-level padding PADT(i)=i+(i>>4)+(i>>8).
// Unpadded tw loads at stride 16/64 float2 were 16-32-way bank conflicted
// (~12.5K cyc/CTA, as much as ALL data traffic). Every tw access pattern is
// now conflict-free (verified per-lane mod-16 for each stage's index shape).

#define LCONV 8192
#define NFFT  16384
#define LOGN  14
#define NTHR  1024
#define SCALE_F (1.0f / ((float)NFFT * (float)NFFT))

#define PADZ(i) ((i) + ((i) >> 4))
#define ZPAD  (NFFT + (NFFT >> 4))       // 17408 float2
#define PADT(i) ((i) + ((i) >> 4) + ((i) >> 8))
#define TWPAD (4096 + 256 + 16)          // 4368 float2 (max PADT(4095)=4365)

__device__ __forceinline__ float2 cmul(float2 a, float2 b) {
    return make_float2(fmaf(a.x, b.x, -a.y * b.y),
                       fmaf(a.x, b.y,  a.y * b.x));
}
__device__ __forceinline__ float2 cadd(float2 a, float2 b) {
    return make_float2(a.x + b.x, a.y + b.y);
}
__device__ __forceinline__ float2 csub(float2 a, float2 b) {
    return make_float2(a.x - b.x, a.y - b.y);
}

__device__ __forceinline__ void dif4(float2& x0, float2& x1, float2& x2, float2& x3) {
    float2 t02p = cadd(x0, x2), t02m = csub(x0, x2);
    float2 t13p = cadd(x1, x3), t13m = csub(x1, x3);
    float2 mi13 = make_float2(t13m.y, -t13m.x);       // -i*(x1-x3)
    x0 = cadd(t02p, t13p);
    x1 = cadd(t02m, mi13);
    x2 = csub(t02p, t13p);
    x3 = csub(t02m, mi13);
}

__device__ __forceinline__ void dit4(float2& x0, float2& x1, float2& x2, float2& x3) {
    float2 s02p = cadd(x0, x2), s02m = csub(x0, x2);
    float2 s13p = cadd(x1, x3), s13m = csub(x1, x3);
    float2 pi13 = make_float2(-s13m.y, s13m.x);       // +i*(x1-x3)
    x0 = cadd(s02p, s13p);
    x1 = cadd(s02m, pi13);
    x2 = csub(s02p, s13p);
    x3 = csub(s02m, pi13);
}

// pointwise unpack+multiply for a Hermitian pair; orientation-free
__device__ __forceinline__ void pw(float2& za, float2& zb) {
    float2 X = make_float2(0.5f * (za.x + zb.x), 0.5f * (za.y - zb.y));
    float2 d = make_float2(za.x - zb.x, za.y + zb.y);
    float2 H = make_float2(0.5f * d.y, -0.5f * d.x);
    float2 Y = cmul(X, H);
    Y.x *= SCALE_F; Y.y *= SCALE_F;
    za = Y;
    zb = make_float2(Y.x, -Y.y);
}

// one fused middle item; pga/pgb are PRE-PADDED base addresses
__device__ __forceinline__ void pair_item(float2* z, int pga, int pgb) {
    float2 a0 = z[pga], a1 = z[pga + 1], a2 = z[pga + 2], a3 = z[pga + 3];
    float2 b0 = z[pgb], b1 = z[pgb + 1], b2 = z[pgb + 2], b3 = z[pgb + 3];
    dif4(a0, a1, a2, a3);
    dif4(b0, b1, b2, b3);
    pw(a0, b3); pw(a1, b2); pw(a2, b1); pw(a3, b0);
    dit4(a0, a1, a2, a3);
    dit4(b0, b1, b2, b3);
    z[pga] = a0; z[pga + 1] = a1; z[pga + 2] = a2; z[pga + 3] = a3;
    z[pgb] = b0; z[pgb + 1] = b1; z[pgb + 2] = b2; z[pgb + 3] = b3;
}

// generic fused fwd radix-16 stage (spans LM and LM-2), compile-time LM
template<int LM>
__device__ __forceinline__ void fwd16(float2* __restrict__ z,
                                      const float2* __restrict__ tw, int tid) {
    constexpr int LQ = LM - 4;
    constexpr int QP = 1 << LQ;
    constexpr int Q  = QP << 2;
    constexpr int TS = LOGN - LM;
    const int j    = tid & (QP - 1);
    const int base = ((tid >> LQ) << LM) + j;
    const int pb   = PADZ(base);
    float2 v[4][4];
    #pragma unroll
    for (int a = 0; a < 4; ++a)
        #pragma unroll
        for (int b = 0; b < 4; ++b) {
            const int off = a * Q + b * QP;          // compile-time
            v[a][b] = z[pb + off + (off >> 4)];
        }
    #pragma unroll
    for (int b = 0; b < 4; ++b) {
        float2 w1 = tw[PADT((j + b * QP) << TS)];
        float2 w2 = cmul(w1, w1);
        float2 w3 = cmul(w2, w1);
        dif4(v[0][b], v[1][b], v[2][b], v[3][b]);
        v[1][b] = cmul(v[1][b], w1);
        v[2][b] = cmul(v[2][b], w2);
        v[3][b] = cmul(v[3][b], w3);
    }
    {
        float2 w1 = tw[PADT(j << (TS + 2))];
        float2 w2 = cmul(w1, w1);
        float2 w3 = cmul(w2, w1);
        #pragma unroll
        for (int a = 0; a < 4; ++a) {
            dif4(v[a][0], v[a][1], v[a][2], v[a][3]);
            v[a][1] = cmul(v[a][1], w1);
            v[a][2] = cmul(v[a][2], w2);
            v[a][3] = cmul(v[a][3], w3);
        }
    }
    #pragma unroll
    for (int a = 0; a < 4; ++a)
        #pragma unroll
        for (int b = 0; b < 4; ++b) {
            const int off = a * Q + b * QP;
            z[pb + off + (off >> 4)] = v[a][b];
        }
}

// generic fused inverse radix-16 stage (spans LMS and LMS+2), compile-time LMS
template<int LMS>
__device__ __forceinline__ void inv16(float2* __restrict__ z,
                                      const float2* __restrict__ tw, int tid) {
    constexpr int LQS = LMS - 2;
    constexpr int QS  = 1 << LQS;
    constexpr int QL  = 1 << LMS;
    constexpr int TSS = LOGN - LMS;
    const int j    = tid & (QS - 1);
    const int base = ((tid >> LQS) << (LMS + 2)) + j;
    const int pb   = PADZ(base);
    float2 v[4][4];
    #pragma unroll
    for (int a = 0; a < 4; ++a)
        #pragma unroll
        for (int b = 0; b < 4; ++b) {
            const int off = a * QS + b * QL;
            v[a][b] = z[pb + off + (off >> 4)];
        }
    {
        float2 wc = tw[PADT(j << TSS)];
        float2 w1 = make_float2(wc.x, -wc.y);
        float2 w2 = cmul(w1, w1);
        float2 w3 = cmul(w2, w1);
        #pragma unroll
        for (int b = 0; b < 4; ++b) {
            v[1][b] = cmul(v[1][b], w1);
            v[2][b] = cmul(v[2][b], w2);
            v[3][b] = cmul(v[3][b], w3);
            dit4(v[0][b], v[1][b], v[2][b], v[3][b]);
        }
    }
    #pragma unroll
    for (int a = 0; a < 4; ++a) {
        float2 wc = tw[PADT((j + a * QS) << (TSS - 2))];
        float2 w1 = make_float2(wc.x, -wc.y);
        float2 w2 = cmul(w1, w1);
        float2 w3 = cmul(w2, w1);
        v[a][1] = cmul(v[a][1], w1);
        v[a][2] = cmul(v[a][2], w2);
        v[a][3] = cmul(v[a][3], w3);
        dit4(v[a][0], v[a][1], v[a][2], v[a][3]);
    }
    #pragma unroll
    for (int a = 0; a < 4; ++a)
        #pragma unroll
        for (int b = 0; b < 4; ++b) {
            const int off = a * QS + b * QL;
            z[pb + off + (off >> 4)] = v[a][b];
        }
}

extern "C" __global__ void __launch_bounds__(NTHR, 1)
fftconv_kernel(const float* __restrict__ xin,
               const float* __restrict__ hin,
               float* __restrict__ yout)
{
    extern __shared__ float2 sm[];
    float2* z  = sm;           // ZPAD float2 (padded data)
    float2* tw = sm + ZPAD;    // TWPAD float2 (padded twiddles)

    const int tid = threadIdx.x;
    const size_t row = blockIdx.x;
    const float* xr = xin + row * LCONV;
    const float* hr = hin + row * LCONV;
    float* yr = yout + row * LCONV;

    // ---- stage-1 gmem loads, issued early so LDG hides under sincos ----
    float2 in0[4], in1[4];
    #pragma unroll
    for (int b = 0; b < 4; ++b) {
        const int i0 = tid + (b << 10);
        in0[b] = make_float2(xr[i0], hr[i0]);
        const int i1 = i0 + 4096;
        in1[b] = make_float2(xr[i1], hr[i1]);
    }

    // ---- twiddles: tw[PADT(t)] = exp(-2*pi*i*t/N), t in [0, N/4) ----
    {
        const float step = -6.28318530717958647692f / (float)NFFT;
        #pragma unroll
        for (int t = tid; t < NFFT / 4; t += NTHR) {
            float s, c;
            __sincosf(step * (float)t, &s, &c);
            tw[PADT(t)] = make_float2(c, s);
        }
    }
    __syncthreads();

    // ---- fwd stage lm=14, fused with input; indices >= 8192 are zero ----
    {
        const int j  = tid;
        const int pb = PADZ(j);
        float2 v[4][4];
        #pragma unroll
        for (int b = 0; b < 4; ++b) {
            float2 x0 = in0[b], x1 = in1[b];
            float2 w1 = tw[PADT(j + (b << 10))];
            float2 w2 = cmul(w1, w1);
            float2 w3 = cmul(w2, w1);
            v[0][b] = cadd(x0, x1);
            v[1][b] = cmul(make_float2(x0.x + x1.y, x0.y - x1.x), w1); // x0 - i*x1
            v[2][b] = cmul(csub(x0, x1), w2);
            v[3][b] = cmul(make_float2(x0.x - x1.y, x0.y + x1.x), w3); // x0 + i*x1
        }
        float2 w1 = tw[PADT(j << 2)];
        float2 w2 = cmul(w1, w1);
        float2 w3 = cmul(w2, w1);
        #pragma unroll
        for (int a = 0; a < 4; ++a) {
            dif4(v[a][0], v[a][1], v[a][2], v[a][3]);
            v[a][1] = cmul(v[a][1], w1);
            v[a][2] = cmul(v[a][2], w2);
            v[a][3] = cmul(v[a][3], w3);
        }
        #pragma unroll
        for (int a = 0; a < 4; ++a)
            #pragma unroll
            for (int b = 0; b < 4; ++b) {
                const int off = a * 4096 + b * 1024;
                z[pb + off + (off >> 4)] = v[a][b];
            }
    }
    __syncthreads();

    // ---- fwd stages lm = 10, 6 ----
    fwd16<10>(z, tw, tid);
    __syncthreads();
    fwd16<6>(z, tw, tid);
    __syncthreads();

    // ---- FUSED middle: fwd lm=2 radix-4 + pointwise + inv lm=2 radix-4 ----
    {
        #pragma unroll 1
        for (int m = LOGN; m >= 4; m -= 2) {
            const int S4 = 1 << (m - 2);
            // branch 1: [S4, 2*S4) <-> [3*S4, 4*S4)
            #pragma unroll 1
            for (int it = tid; it < (S4 >> 2); it += NTHR) {
                const int ga = S4 + 4 * it;
                const int gb = 4 * S4 - 4 - 4 * it;
                pair_item(z, PADZ(ga), PADZ(gb));
            }
            // branch 2: [2*S4, 3*S4) pairs internally (needs >= 2 groups)
            if (S4 >= 16) {
                #pragma unroll 1
                for (int it = tid; it < (S4 >> 3); it += NTHR) {
                    const int ga = 2 * S4 + 4 * it;
                    const int gb = 3 * S4 - 4 - 4 * it;
                    pair_item(z, PADZ(ga), PADZ(gb));
                }
            }
        }
        // special: group [0..3] (selfs k=0 @0, k=N/2 @2; pair (1,3))
        if (tid == NTHR - 1) {
            float2 a0 = z[0], a1 = z[1], a2 = z[2], a3 = z[3];
            dif4(a0, a1, a2, a3);
            a0 = make_float2(a0.x * a0.y * SCALE_F, 0.0f);
            a2 = make_float2(a2.x * a2.y * SCALE_F, 0.0f);
            pw(a1, a3);
            dit4(a0, a1, a2, a3);
            z[0] = a0; z[1] = a1; z[2] = a2; z[3] = a3;
        }
        // special: group [8..11] (S4=4 middle; pairs (8,11),(9,10))
        if (tid == NTHR - 2) {
            float2 a0 = z[8], a1 = z[9], a2 = z[10], a3 = z[11];
            dif4(a0, a1, a2, a3);
            pw(a0, a3); pw(a1, a2);
            dit4(a0, a1, a2, a3);
            z[8] = a0; z[9] = a1; z[10] = a2; z[11] = a3;
        }
    }
    __syncthreads();

    // ---- inverse stages lm_s = 4, 8 ----
    inv16<4>(z, tw, tid);
    __syncthreads();
    inv16<8>(z, tw, tid);
    __syncthreads();

    // ---- inverse stage lm_s = 12, fused with gmem store ----
    // outputs at j + 1024*a + 4096*b; b in {0,1} covers [0, 8192) exactly.
    {
        const int j  = tid;      // qs = 1024, ql = 4096, tss = 2
        const int pb = PADZ(j);
        float2 v[4][4];
        #pragma unroll
        for (int a = 0; a < 4; ++a)
            #pragma unroll
            for (int b = 0; b < 4; ++b) {
                const int off = (a << 10) + (b << 12);
                v[a][b] = z[pb + off + (off >> 4)];
            }
        {
            float2 wc = tw[PADT(j << 2)];
            float2 w1 = make_float2(wc.x, -wc.y);
            float2 w2 = cmul(w1, w1);
            float2 w3 = cmul(w2, w1);
            #pragma unroll
            for (int b = 0; b < 4; ++b) {
                v[1][b] = cmul(v[1][b], w1);
                v[2][b] = cmul(v[2][b], w2);
                v[3][b] = cmul(v[3][b], w3);
                dit4(v[0][b], v[1][b], v[2][b], v[3][b]);
            }
        }
        #pragma unroll
        for (int a = 0; a < 4; ++a) {
            float2 wc = tw[PADT(j + (a << 10))];
            float2 w1 = make_float2(wc.x, -wc.y);
            float2 w2 = cmul(w1, w1);
            float2 w3 = cmul(w2, w1);
            float2 c0 = v[a][0];
            float2 c1 = cmul(v[a][1], w1);
            float  c2x = fmaf(v[a][2].x, w2.x, -v[a][2].y * w2.y);  // Re only
            float2 c3 = cmul(v[a][3], w3);
            // b=0: Re(s02p + s13p); b=1: Re(s02m + i*(c1-c3))
            float y0 = (c0.x + c2x) + (c1.x + c3.x);
            float y1 = (c0.x - c2x) - (c1.y - c3.y);
            yr[j + (a << 10)]        = y0;
            yr[j + (a << 10) + 4096] = y1;
        }
    }
}

extern "C" void kernel_launch(void* const* d_in, const int* in_sizes, int n_in,
                              void* d_out, int out_size) {
    const float* x = (const float*)d_in[0];
    const float* h = (const float*)d_in[1];
    float* y = (float*)d_out;

    const int B = in_sizes[0] / LCONV;
    const size_t smem_bytes = (size_t)(ZPAD + TWPAD) * sizeof(float2);  // ~174 KB

    cudaFuncSetAttribute(fftconv_kernel,
                         cudaFuncAttributeMaxDynamicSharedMemorySize,
                         (int)smem_bytes);
    fftconv_kernel<<<B, NTHR, smem_bytes>>>(x, h, y);
}